// round 2
// baseline (speedup 1.0000x reference)
#include <cuda_runtime.h>
#include <cstdint>

// Problem constants (fixed-shape problem)
#define NC   200000
#define NF   800000
#define NE   3200000
#define NEP  2400000
#define CIN  128
#define COUT 64

// Scratch: h (self term + edge aggregation) and m (neighbor transform).
// __device__ globals per allocation-guard rules.
__device__ float g_h[(size_t)NC * COUT];
__device__ float g_m[(size_t)NC * COUT];

// ---------------------------------------------------------------------------
// K1: h = x @ W_root + b ; m = x @ W_nbr
// Block: 256 threads = 64 cols x 4 row-subgroups; each thread does 4 rows.
// Both weight matrices staged in smem (64KB), x tiles (16 rows) staged too.
// ---------------------------------------------------------------------------
__global__ void k_gemm(const float* __restrict__ x,
                       const float* __restrict__ Wr,
                       const float* __restrict__ Wn,
                       const float* __restrict__ bias,
                       int n_rows) {
    extern __shared__ float sm[];
    float* sWr = sm;                    // 8192 floats (32KB)
    float* sWn = sm + CIN * COUT;       // 8192 floats (32KB)
    float* sx  = sm + 2 * CIN * COUT;   // 16*128 = 2048 floats (8KB)

    for (int i = threadIdx.x; i < CIN * COUT; i += blockDim.x) {
        sWr[i] = Wr[i];
        sWn[i] = Wn[i];
    }
    __syncthreads();

    const int col = threadIdx.x & 63;
    const int sub = threadIdx.x >> 6;   // 0..3
    const float bcol = bias[col];

    for (int tile = blockIdx.x * 16; tile < n_rows; tile += gridDim.x * 16) {
        const int nrows = min(16, n_rows - tile);

        __syncthreads();  // protect sx from previous iteration readers
        for (int i = threadIdx.x * 4; i < nrows * CIN; i += blockDim.x * 4) {
            *(float4*)&sx[i] = *(const float4*)&x[(size_t)tile * CIN + i];
        }
        __syncthreads();

        float ah[4], am[4];
#pragma unroll
        for (int j = 0; j < 4; j++) { ah[j] = bcol; am[j] = 0.f; }

#pragma unroll 4
        for (int k = 0; k < CIN; k++) {
            const float wr = sWr[k * COUT + col];
            const float wn = sWn[k * COUT + col];
#pragma unroll
            for (int j = 0; j < 4; j++) {
                const float xv = sx[(sub * 4 + j) * CIN + k];
                ah[j] = fmaf(xv, wr, ah[j]);
                am[j] = fmaf(xv, wn, am[j]);
            }
        }

#pragma unroll
        for (int j = 0; j < 4; j++) {
            const int r = tile + sub * 4 + j;
            if (r < n_rows) {
                g_h[(size_t)r * COUT + col] = ah[j];
                g_m[(size_t)r * COUT + col] = am[j];
            }
        }
    }
}

// ---------------------------------------------------------------------------
// K2: edge aggregation: h[dst] += m[src] * edge_attr   (16 threads per edge,
// float4 per thread, vector red.global). Indices are int32 (JAX canonicalizes
// int64 -> int32 without x64 mode).
// ---------------------------------------------------------------------------
__global__ void k_edge(const int* __restrict__ src,
                       const int* __restrict__ dst,
                       const float* __restrict__ ea,
                       int nE) {
    const long long t = (long long)blockIdx.x * blockDim.x + threadIdx.x;
    const int e = (int)(t >> 4);
    if (e >= nE) return;
    const int c = (int)(t & 15) << 2;  // channel base (0,4,...,60)

    const int s = src[e];
    const int d = dst[e];
    const float w = ea[e];

    const float4 v = *(const float4*)&g_m[(size_t)s * COUT + c];
    float* p = &g_h[(size_t)d * COUT + c];
    asm volatile("red.global.add.v4.f32 [%0], {%1,%2,%3,%4};"
                 :: "l"(p), "f"(v.x * w), "f"(v.y * w), "f"(v.z * w), "f"(v.w * w)
                 : "memory");
}

// ---------------------------------------------------------------------------
// K3: unpooling: out[pool_dst] += h[pool_src] * pool_edge_attr
// ---------------------------------------------------------------------------
__global__ void k_pool(const int* __restrict__ src,
                       const int* __restrict__ dst,
                       const float* __restrict__ ea,
                       float* __restrict__ out,
                       int nE) {
    const long long t = (long long)blockIdx.x * blockDim.x + threadIdx.x;
    const int e = (int)(t >> 4);
    if (e >= nE) return;
    const int c = (int)(t & 15) << 2;

    const int s = src[e];
    const int d = dst[e];
    const float w = ea[e];

    const float4 v = *(const float4*)&g_h[(size_t)s * COUT + c];
    float* p = &out[(size_t)d * COUT + c];
    asm volatile("red.global.add.v4.f32 [%0], {%1,%2,%3,%4};"
                 :: "l"(p), "f"(v.x * w), "f"(v.y * w), "f"(v.z * w), "f"(v.w * w)
                 : "memory");
}

// ---------------------------------------------------------------------------
// Launch. Inputs (metadata order):
// 0: x [NC,128] f32      1: W_root [128,64] f32   2: W_nbr [128,64] f32
// 3: b [64] f32          4: edge_index [2,NE] i32 5: edge_attr [NE,1] f32
// 6: pool_src [NEP] i32  7: pool_dst [NEP] i32    8: pool_edge_attr [NEP,1] f32
// 9: n_fine scalar
// out: [NF, 64] f32
// ---------------------------------------------------------------------------
extern "C" void kernel_launch(void* const* d_in, const int* in_sizes, int n_in,
                              void* d_out, int out_size) {
    const float* x   = (const float*)d_in[0];
    const float* Wr  = (const float*)d_in[1];
    const float* Wn  = (const float*)d_in[2];
    const float* b   = (const float*)d_in[3];
    const int*   ei  = (const int*)d_in[4];
    const float* ea  = (const float*)d_in[5];
    const int*   ps  = (const int*)d_in[6];
    const int*   pd  = (const int*)d_in[7];
    const float* pea = (const float*)d_in[8];
    float*       out = (float*)d_out;

    const int smem = (2 * CIN * COUT + 16 * CIN) * sizeof(float);  // 73728
    cudaFuncSetAttribute(k_gemm, cudaFuncAttributeMaxDynamicSharedMemorySize, smem);

    k_gemm<<<444, 256, smem>>>(x, Wr, Wn, b, NC);

    cudaMemsetAsync(d_out, 0, (size_t)out_size * sizeof(float));

    {
        const long long threads = (long long)NE * 16;
        const int grid = (int)((threads + 255) / 256);
        k_edge<<<grid, 256>>>(ei, ei + NE, ea, NE);
    }
    {
        const long long threads = (long long)NEP * 16;
        const int grid = (int)((threads + 255) / 256);
        k_pool<<<grid, 256>>>(ps, pd, pea, out, NEP);
    }
}

// round 3
// speedup vs baseline: 1.1353x; 1.1353x over previous
#include <cuda_runtime.h>
#include <cstdint>

// Problem constants (fixed-shape problem)
#define NC   200000
#define NF   800000
#define NE   3200000
#define NEP  2400000
#define CIN  128
#define COUT 64
#define XS   132            // padded x row stride in smem (conflict-free)
#define NTILES (NC / 64)    // 3125 row-tiles of 64

// Scratch: h (self term + edge aggregation) and m (neighbor transform).
__device__ float g_h[(size_t)NC * COUT];
__device__ float g_m[(size_t)NC * COUT];

typedef unsigned long long ull;

__device__ __forceinline__ ull pack2(float a, float b) {
    ull r;
    asm("mov.b64 %0, {%1, %2};" : "=l"(r) : "f"(a), "f"(b));
    return r;
}
__device__ __forceinline__ void ffma2(ull& d, ull a, ull b) {
    asm("fma.rn.f32x2 %0, %1, %2, %3;" : "=l"(d) : "l"(a), "l"(b), "l"(d));
}

// ---------------------------------------------------------------------------
// K1: h = x @ W_root + b ; m = x @ W_nbr
// Persistent blocks. Tile = 64 rows x 64 cols. 256 threads, each computes
// 4 rows x 4 cols for BOTH outputs, accumulating in packed f32x2 pairs.
// ---------------------------------------------------------------------------
__global__ void __launch_bounds__(256, 2)
k_gemm(const float* __restrict__ x,
       const float* __restrict__ Wr,
       const float* __restrict__ Wn,
       const float* __restrict__ bias) {
    extern __shared__ float sm[];
    float* sWr = sm;                    // 8192 floats
    float* sWn = sm + CIN * COUT;       // 8192 floats
    float* sx  = sm + 2 * CIN * COUT;   // 64 * 132 floats

    for (int i = threadIdx.x * 4; i < CIN * COUT; i += blockDim.x * 4) {
        *(float4*)&sWr[i] = *(const float4*)&Wr[i];
        *(float4*)&sWn[i] = *(const float4*)&Wn[i];
    }

    const int cg = threadIdx.x & 15;    // col group: cols 4*cg .. 4*cg+3
    const int rg = threadIdx.x >> 4;    // row group: rows 4*rg .. 4*rg+3

    const float4 bv = *(const float4*)&bias[cg * 4];
    const ull bh0 = pack2(bv.x, bv.y);
    const ull bh1 = pack2(bv.z, bv.w);

    for (int tile = blockIdx.x; tile < NTILES; tile += gridDim.x) {
        const int row0 = tile * 64;

        __syncthreads();  // protect sx/sW from previous-iteration readers
        for (int i = threadIdx.x; i < 64 * (CIN / 4); i += blockDim.x) {
            const int r = i >> 5;
            const int c = (i & 31) << 2;
            *(float4*)&sx[r * XS + c] =
                *(const float4*)&x[(size_t)(row0 + r) * CIN + c];
        }
        __syncthreads();

        ull ah[4][2], am[4][2];
#pragma unroll
        for (int j = 0; j < 4; j++) {
            ah[j][0] = bh0; ah[j][1] = bh1;
            am[j][0] = 0ull; am[j][1] = 0ull;
        }

#pragma unroll 2
        for (int k4 = 0; k4 < CIN / 4; k4++) {
            float4 xv[4];
#pragma unroll
            for (int j = 0; j < 4; j++)
                xv[j] = *(const float4*)&sx[(rg * 4 + j) * XS + k4 * 4];

#pragma unroll
            for (int kk = 0; kk < 4; kk++) {
                const int k = k4 * 4 + kk;
                const ulonglong2 wr = *(const ulonglong2*)&sWr[k * COUT + cg * 4];
                const ulonglong2 wn = *(const ulonglong2*)&sWn[k * COUT + cg * 4];
#pragma unroll
                for (int j = 0; j < 4; j++) {
                    const float xs = (kk == 0) ? xv[j].x : (kk == 1) ? xv[j].y
                                   : (kk == 2) ? xv[j].z : xv[j].w;
                    const ull xp = pack2(xs, xs);
                    ffma2(ah[j][0], xp, wr.x);
                    ffma2(ah[j][1], xp, wr.y);
                    ffma2(am[j][0], xp, wn.x);
                    ffma2(am[j][1], xp, wn.y);
                }
            }
        }

#pragma unroll
        for (int j = 0; j < 4; j++) {
            const size_t r = (size_t)(row0 + rg * 4 + j);
            ulonglong2 vh; vh.x = ah[j][0]; vh.y = ah[j][1];
            ulonglong2 vm; vm.x = am[j][0]; vm.y = am[j][1];
            *(ulonglong2*)&g_h[r * COUT + cg * 4] = vh;
            *(ulonglong2*)&g_m[r * COUT + cg * 4] = vm;
        }
    }
}

// ---------------------------------------------------------------------------
// K2: edge aggregation: h[dst] += m[src] * edge_attr   (16 threads/edge,
// float4 vector red.global). Indices are int32.
// ---------------------------------------------------------------------------
__global__ void k_edge(const int* __restrict__ src,
                       const int* __restrict__ dst,
                       const float* __restrict__ ea,
                       int nE) {
    const long long t = (long long)blockIdx.x * blockDim.x + threadIdx.x;
    const int e = (int)(t >> 4);
    if (e >= nE) return;
    const int c = (int)(t & 15) << 2;

    const int s = src[e];
    const int d = dst[e];
    const float w = ea[e];

    const float4 v = *(const float4*)&g_m[(size_t)s * COUT + c];
    float* p = &g_h[(size_t)d * COUT + c];
    asm volatile("red.global.add.v4.f32 [%0], {%1,%2,%3,%4};"
                 :: "l"(p), "f"(v.x * w), "f"(v.y * w), "f"(v.z * w), "f"(v.w * w)
                 : "memory");
}

// ---------------------------------------------------------------------------
// K3: unpooling: out[pool_dst] += h[pool_src] * pool_edge_attr
// ---------------------------------------------------------------------------
__global__ void k_pool(const int* __restrict__ src,
                       const int* __restrict__ dst,
                       const float* __restrict__ ea,
                       float* __restrict__ out,
                       int nE) {
    const long long t = (long long)blockIdx.x * blockDim.x + threadIdx.x;
    const int e = (int)(t >> 4);
    if (e >= nE) return;
    const int c = (int)(t & 15) << 2;

    const int s = src[e];
    const int d = dst[e];
    const float w = ea[e];

    const float4 v = *(const float4*)&g_h[(size_t)s * COUT + c];
    float* p = &out[(size_t)d * COUT + c];
    asm volatile("red.global.add.v4.f32 [%0], {%1,%2,%3,%4};"
                 :: "l"(p), "f"(v.x * w), "f"(v.y * w), "f"(v.z * w), "f"(v.w * w)
                 : "memory");
}

// ---------------------------------------------------------------------------
// Launch. Inputs (metadata order):
// 0: x [NC,128] f32      1: W_root [128,64] f32   2: W_nbr [128,64] f32
// 3: b [64] f32          4: edge_index [2,NE] i32 5: edge_attr [NE,1] f32
// 6: pool_src [NEP] i32  7: pool_dst [NEP] i32    8: pool_edge_attr [NEP,1] f32
// out: [NF, 64] f32
// ---------------------------------------------------------------------------
extern "C" void kernel_launch(void* const* d_in, const int* in_sizes, int n_in,
                              void* d_out, int out_size) {
    const float* x   = (const float*)d_in[0];
    const float* Wr  = (const float*)d_in[1];
    const float* Wn  = (const float*)d_in[2];
    const float* b   = (const float*)d_in[3];
    const int*   ei  = (const int*)d_in[4];
    const float* ea  = (const float*)d_in[5];
    const int*   ps  = (const int*)d_in[6];
    const int*   pd  = (const int*)d_in[7];
    const float* pea = (const float*)d_in[8];
    float*       out = (float*)d_out;

    const int smem = (2 * CIN * COUT + 64 * XS) * sizeof(float);  // 99328
    cudaFuncSetAttribute(k_gemm, cudaFuncAttributeMaxDynamicSharedMemorySize, smem);

    k_gemm<<<296, 256, smem>>>(x, Wr, Wn, b);

    cudaMemsetAsync(d_out, 0, (size_t)out_size * sizeof(float));

    {
        const long long threads = (long long)NE * 16;
        const int grid = (int)((threads + 255) / 256);
        k_edge<<<grid, 256>>>(ei, ei + NE, ea, NE);
    }
    {
        const long long threads = (long long)NEP * 16;
        const int grid = (int)((threads + 255) / 256);
        k_pool<<<grid, 256>>>(ps, pd, pea, out, NEP);
    }
}